// round 5
// baseline (speedup 1.0000x reference)
#include <cuda_runtime.h>
#include <cstdint>

// Fixed shapes: B=1, N=64, X=256, Y=256, Z=32
#define NINST 64
#define V (256*256*32)                 // 2,097,152 voxels / instance
#define CHUNK_VOX 512                  // voxels per chunk per instance
#define CHUNK_BYTES (CHUNK_VOX*4)      // 2048 B per bulk load
#define CHUNK_WORDS 16                 // packed words per chunk per instance
#define NCHUNK (V/CHUNK_VOX)           // 4096 chunks
#define GROUP 16                       // instances per TMA group / mbarrier
#define HALF_BYTES (GROUP*CHUNK_BYTES) // 32 KB per buffer half
#define NTHR 512
#define NBLK 296                       // 148 SMs * 2 resident blocks
#define NSLOT 8                        // partial accumulator slots

// Dynamic smem layout
#define SM_RAW     0
#define SM_PACKED  (2*HALF_BYTES)                      // 65536
#define SM_MBAR    (SM_PACKED + CHUNK_WORDS*NINST*4)   // 69632
#define SM_CHUNK   (SM_MBAR + 16)                      // 69648
#define SM_TOTAL   69664

// Device state (zero-initialized at load; the last block of every launch
// restores it to zero, so graph replays start clean).
__device__ unsigned g_partial[NSLOT * NINST * NINST];
__device__ unsigned g_ticket;
__device__ unsigned g_done;

// ---------------------------------------------------------------------------
// PTX helpers
// ---------------------------------------------------------------------------
__device__ __forceinline__ unsigned su32(const void* p) {
    return (unsigned)__cvta_generic_to_shared(p);
}
__device__ __forceinline__ void mbar_init(unsigned a, unsigned cnt) {
    asm volatile("mbarrier.init.shared.b64 [%0], %1;" :: "r"(a), "r"(cnt) : "memory");
}
__device__ __forceinline__ void mbar_expect_tx(unsigned a, unsigned tx) {
    asm volatile("mbarrier.arrive.expect_tx.shared.b64 _, [%0], %1;"
                 :: "r"(a), "r"(tx) : "memory");
}
__device__ __forceinline__ void mbar_wait(unsigned a, unsigned parity) {
    asm volatile(
        "{\n\t.reg .pred p;\n\t"
        "WAIT_%=:\n\t"
        "mbarrier.try_wait.parity.acquire.cta.shared::cta.b64 p, [%0], %1, 0x989680;\n\t"
        "@!p bra WAIT_%=;\n\t}"
        :: "r"(a), "r"(parity) : "memory");
}
__device__ __forceinline__ void tma_bulk(unsigned dst, const void* src,
                                         unsigned bytes, unsigned mbar) {
    asm volatile(
        "cp.async.bulk.shared::cta.global.mbarrier::complete_tx::bytes [%0], [%1], %2, [%3];"
        :: "r"(dst), "l"(src), "r"(bytes), "r"(mbar) : "memory");
}
__device__ __forceinline__ void fence_async() {
    asm volatile("fence.proxy.async.shared::cta;" ::: "memory");
}

// ---------------------------------------------------------------------------
// Single fused kernel.  Work map (512 units, warp-uniform):
//   tid <  480 : off-diagonal upper 4x4 tile (a<b), quarter q -> words [4q,4q+4)
//   tid >= 480 : diagonal 4x4 tile (a,a),      half  h -> words [8h,8h+8)
// Only upper-triangle tiles are accumulated; the reduce symmetrizes with max.
// ---------------------------------------------------------------------------
extern __shared__ char smem[];

__global__ __launch_bounds__(NTHR) void fused_nms_kernel(
    const float* __restrict__ mask, float* __restrict__ out)
{
    const unsigned sbase = su32(smem);
    unsigned (*packed)[NINST] = (unsigned (*)[NINST])(smem + SM_PACKED);
    int* s_chunk = (int*)(smem + SM_CHUNK);
    const unsigned mb[2] = {sbase + SM_MBAR, sbase + SM_MBAR + 8};

    const int tid  = threadIdx.x;
    const int lane = tid & 31;
    const int wp   = tid >> 5;          // 16 warps

    if (tid == 0) {
        mbar_init(mb[0], 1);
        mbar_init(mb[1], 1);
        fence_async();
    }

    // ----- triangular work-unit decode (once) -----
    int ti, tj, w_start, w_end;
    if (tid < 480) {
        int k = tid >> 2;               // off-diag tile id in [0,120)
        int q = tid & 3;
        int a = 0, rem = k;
        while (rem >= 15 - a) { rem -= 15 - a; a++; }
        ti = a; tj = a + 1 + rem;
        w_start = q * 4; w_end = w_start + 4;
    } else {
        int d = (tid - 480) >> 1;       // diagonal tile id in [0,16)
        int h = tid & 1;
        ti = d; tj = d;
        w_start = h * 8; w_end = w_start + 8;
    }
    const int i0 = ti * 4, j0 = tj * 4;

    unsigned acc[4][4];
#pragma unroll
    for (int r = 0; r < 4; r++)
#pragma unroll
        for (int c2 = 0; c2 < 4; c2++) acc[r][c2] = 0u;

    // tid0: issue one group (16 instances x 2KB) into buffer half hb.
    auto issue = [&](int g, int hb, int c) {
        const float* src = mask + (size_t)c * CHUNK_VOX + (size_t)(g * GROUP) * V;
        const unsigned dst = sbase + SM_RAW + hb * HALF_BYTES;
        mbar_expect_tx(mb[hb], HALF_BYTES);
#pragma unroll
        for (int jj = 0; jj < GROUP; jj++)
            tma_bulk(dst + jj * CHUNK_BYTES, src + (size_t)jj * V,
                     CHUNK_BYTES, mb[hb]);
    };

    // Prologue: first ticket + groups 0,1 in flight.
    if (tid == 0) {
        int t0 = (int)atomicAdd(&g_ticket, 1u);
        *s_chunk = t0;
        if (t0 < NCHUNK) { issue(0, 0, t0); issue(1, 1, t0); }
    }
    __syncthreads();
    int c = *s_chunk;

    // Pack read address: warp wp owns word wp; lane reads voxel wp*32+lane.
    const unsigned raw_rd = sbase + SM_RAW + (unsigned)(wp * 128 + lane * 4);
    unsigned ph0 = 0, ph1 = 0;
    int nextc = NCHUNK;  // tid0-local

    while (c < NCHUNK) {
#pragma unroll
        for (int g = 0; g < 4; g++) {
            const int hb = g & 1;
            if (hb == 0) { mbar_wait(mb[0], ph0); ph0 ^= 1; }
            else         { mbar_wait(mb[1], ph1); ph1 ^= 1; }

            // Pack 16 instances: warp wp packs word wp for each instance.
            const unsigned rbase = raw_rd + (unsigned)hb * HALF_BYTES;
#pragma unroll
            for (int jj = 0; jj < GROUP; jj++) {
                unsigned v;
                asm volatile("ld.shared.u32 %0, [%1];"
                             : "=r"(v)
                             : "r"(rbase + (unsigned)jj * CHUNK_BYTES));
                unsigned b0 = __ballot_sync(0xffffffffu, v != 0u);
                if (lane == 0) packed[wp][g * GROUP + jj] = b0;
            }
            __syncthreads();  // half hb fully consumed; packed cols visible

            if (tid == 0) {
                fence_async();  // order generic reads before async refill
                if (g == 0)      issue(2, 0, c);
                else if (g == 1) issue(3, 1, c);
                else if (g == 2) {
                    nextc = (int)atomicAdd(&g_ticket, 1u);
                    *s_chunk = nextc;   // published by g3's __syncthreads
                    if (nextc < NCHUNK) issue(0, 0, nextc);
                } else {
                    if (nextc < NCHUNK) issue(1, 1, nextc);
                }
            }
        }

        // Phase B: this thread's word span on its (upper-triangle) tile.
#pragma unroll 1
        for (int w = w_start; w < w_end; w += 2) {
            uint4 A0 = *(const uint4*)&packed[w][i0];
            uint4 B0 = *(const uint4*)&packed[w][j0];
            uint4 A1 = *(const uint4*)&packed[w + 1][i0];
            uint4 B1 = *(const uint4*)&packed[w + 1][j0];
            unsigned a0[4] = {A0.x, A0.y, A0.z, A0.w};
            unsigned b0[4] = {B0.x, B0.y, B0.z, B0.w};
            unsigned a1[4] = {A1.x, A1.y, A1.z, A1.w};
            unsigned b1[4] = {B1.x, B1.y, B1.z, B1.w};
#pragma unroll
            for (int r = 0; r < 4; r++)
#pragma unroll
                for (int c2 = 0; c2 < 4; c2++)
                    acc[r][c2] += __popc(a0[r] & b0[c2]) + __popc(a1[r] & b1[c2]);
        }
        __syncthreads();  // protect packed[] against next chunk's pack writes
        c = *s_chunk;
    }

    // Flush per-block totals (upper-triangle addresses only).
    {
        unsigned* gp =
            g_partial + (unsigned)(blockIdx.x & (NSLOT - 1)) * (NINST * NINST);
#pragma unroll
        for (int r = 0; r < 4; r++)
#pragma unroll
            for (int c2 = 0; c2 < 4; c2++)
                atomicAdd(&gp[(i0 + r) * NINST + (j0 + c2)], acc[r][c2]);
    }
    __threadfence();
    __syncthreads();
    if (tid == 0) *s_chunk = (int)atomicAdd(&g_done, 1u);
    __syncthreads();
    if (*s_chunk != NBLK - 1) return;

    // ------------------- Last block: reduce + NMS + reset -------------------
    unsigned* inter = (unsigned*)smem;             // 16 KB (raw area is dead)
    unsigned* ssc   = (unsigned*)(smem + 16384);

    {   // vectorized reduce of NSLOT slots (L1-bypassing loads)
        const uint4* gp4 = (const uint4*)g_partial;   // [NSLOT][1024] uint4
        uint4* in4 = (uint4*)inter;
        for (int e = tid; e < (NINST * NINST) / 4; e += NTHR) {
            uint4 s = make_uint4(0u, 0u, 0u, 0u);
#pragma unroll
            for (int k = 0; k < NSLOT; k++) {
                uint4 v = __ldcg(&gp4[k * (NINST * NINST / 4) + e]);
                s.x += v.x; s.y += v.y; s.z += v.z; s.w += v.w;
            }
            in4[e] = s;
        }
    }
    __syncthreads();

    {   // symmetrize: lower-triangle tiles were never written (zeros);
        // diag-tile mirror cells carry equal full values -> max is correct.
        for (int e = tid; e < NINST * NINST; e += NTHR) {
            int i = e >> 6, j = e & 63;
            if (i > j) {
                unsigned hi = inter[j * NINST + i];
                unsigned lo = inter[e];
                inter[e] = hi > lo ? hi : lo;
            }
        }
    }
    __syncthreads();

    {   // reset device state for the next replay
        uint4 z = make_uint4(0u, 0u, 0u, 0u);
        uint4* gz = (uint4*)g_partial;
        for (int e = tid; e < (NSLOT * NINST * NINST) / 4; e += NTHR) gz[e] = z;
        if (tid == 0) { g_ticket = 0u; g_done = 0u; }
    }

    if (tid < NINST) ssc[tid] = inter[tid * NINST + tid];  // score = diagonal
    __syncthreads();

    if (tid < 32) {
        const unsigned sj0 = ssc[lane];
        const unsigned sj1 = ssc[lane + 32];
        unsigned long long ind = ~0ULL;

        for (int i = 0; i < NINST; i++) {
            if (!((ind >> i) & 1ULL)) continue;  // warp-uniform
            const unsigned si  = ssc[i];
            const unsigned in0 = inter[i * NINST + lane];
            const unsigned in1 = inter[i * NINST + lane + 32];
            // iou > 0.5 <=> 2*inter > union (exact integers; counts < 2^23)
            const bool h0 = (2u * in0 > si + sj0 - in0);
            const bool h1 = (2u * in1 > si + sj1 - in1);
            unsigned a0 = __ballot_sync(0xffffffffu, h0 && (si > sj0));
            unsigned a1 = __ballot_sync(0xffffffffu, h1 && (si > sj1));
            unsigned c0 = __ballot_sync(0xffffffffu, h0 && (sj0 > si));
            unsigned c1 = __ballot_sync(0xffffffffu, h1 && (sj1 > si));
            unsigned long long A  = ((unsigned long long)a1 << 32) | a0;
            unsigned long long Bm = ((unsigned long long)c1 << 32) | c0;
            if (A) {
                int jb = __ffsll((long long)A) - 1;   // first break j
                unsigned long long before = (1ULL << jb) - 1ULL;
                if (Bm & before) ind &= ~(1ULL << i); // earlier j beat i first
                ind &= ~(1ULL << jb);
            } else if (Bm) {
                ind &= ~(1ULL << i);
            }
        }
        out[lane]      = (float)((ind >> lane) & 1ULL);
        out[lane + 32] = (float)((ind >> (lane + 32)) & 1ULL);
    }
}

// ---------------------------------------------------------------------------
extern "C" void kernel_launch(void* const* d_in, const int* in_sizes, int n_in,
                              void* d_out, int out_size) {
    const float* mask = (const float*)d_in[0];
    static bool attr_done = false;
    if (!attr_done) {  // host-side attrs: first (pre-capture) call sets them
        cudaFuncSetAttribute(fused_nms_kernel,
                             cudaFuncAttributeMaxDynamicSharedMemorySize,
                             SM_TOTAL);
        cudaFuncSetAttribute(fused_nms_kernel,
                             cudaFuncAttributePreferredSharedMemoryCarveout,
                             cudaSharedmemCarveoutMaxShared);
        attr_done = true;
    }
    fused_nms_kernel<<<NBLK, NTHR, SM_TOTAL>>>(mask, (float*)d_out);
}

// round 6
// speedup vs baseline: 1.1176x; 1.1176x over previous
#include <cuda_runtime.h>
#include <cstdint>

// Fixed shapes: B=1, N=64, X=256, Y=256, Z=32
#define NINST 64
#define V (256*256*32)                 // 2,097,152 voxels / instance
#define CHUNK_VOX 512                  // voxels per chunk per instance
#define CHUNK_BYTES (CHUNK_VOX*4)      // 2048 B per bulk load
#define CHUNK_WORDS 16                 // packed words per chunk per instance
#define NCHUNK (V/CHUNK_VOX)           // 4096 chunks
#define GROUP 16                       // instances per TMA group / mbarrier
#define HALF_BYTES (GROUP*CHUNK_BYTES) // 32 KB per buffer half
#define NTHR 256
#define NBLK 444                       // 148 SMs * 3 resident blocks
#define NSLOT 8                        // partial accumulator slots

// Dynamic smem layout
#define SM_RAW     0
#define SM_PACKED  (2*HALF_BYTES)                      // 65536
#define SM_MBAR    (SM_PACKED + CHUNK_WORDS*NINST*4)   // 69632
#define SM_CHUNK   (SM_MBAR + 16)                      // 69648
#define SM_TOTAL   69664

// Device state (zero-initialized at load; the last block of every launch
// restores it to zero, so graph replays start clean).
__device__ unsigned g_partial[NSLOT * NINST * NINST];
__device__ unsigned g_ticket;
__device__ unsigned g_done;

// ---------------------------------------------------------------------------
// PTX helpers
// ---------------------------------------------------------------------------
__device__ __forceinline__ unsigned su32(const void* p) {
    return (unsigned)__cvta_generic_to_shared(p);
}
__device__ __forceinline__ void mbar_init(unsigned a, unsigned cnt) {
    asm volatile("mbarrier.init.shared.b64 [%0], %1;" :: "r"(a), "r"(cnt) : "memory");
}
__device__ __forceinline__ void mbar_expect_tx(unsigned a, unsigned tx) {
    asm volatile("mbarrier.arrive.expect_tx.shared.b64 _, [%0], %1;"
                 :: "r"(a), "r"(tx) : "memory");
}
__device__ __forceinline__ void mbar_wait(unsigned a, unsigned parity) {
    asm volatile(
        "{\n\t.reg .pred p;\n\t"
        "WAIT_%=:\n\t"
        "mbarrier.try_wait.parity.acquire.cta.shared::cta.b64 p, [%0], %1, 0x989680;\n\t"
        "@!p bra WAIT_%=;\n\t}"
        :: "r"(a), "r"(parity) : "memory");
}
__device__ __forceinline__ void tma_bulk(unsigned dst, const void* src,
                                         unsigned bytes, unsigned mbar) {
    asm volatile(
        "cp.async.bulk.shared::cta.global.mbarrier::complete_tx::bytes [%0], [%1], %2, [%3];"
        :: "r"(dst), "l"(src), "r"(bytes), "r"(mbar) : "memory");
}
__device__ __forceinline__ void fence_async() {
    asm volatile("fence.proxy.async.shared::cta;" ::: "memory");
}

// Fully-unrolled popcount accumulation over NW words starting at w0.
template <int NW>
__device__ __forceinline__ void accum_tile(
    const unsigned (*packed)[NINST], int w0, int i0, int j0,
    unsigned (&acc)[4][4])
{
#pragma unroll
    for (int w = 0; w < NW; w += 2) {
        uint4 A0 = *(const uint4*)&packed[w0 + w][i0];
        uint4 B0 = *(const uint4*)&packed[w0 + w][j0];
        uint4 A1 = *(const uint4*)&packed[w0 + w + 1][i0];
        uint4 B1 = *(const uint4*)&packed[w0 + w + 1][j0];
        unsigned a0[4] = {A0.x, A0.y, A0.z, A0.w};
        unsigned b0[4] = {B0.x, B0.y, B0.z, B0.w};
        unsigned a1[4] = {A1.x, A1.y, A1.z, A1.w};
        unsigned b1[4] = {B1.x, B1.y, B1.z, B1.w};
#pragma unroll
        for (int r = 0; r < 4; r++)
#pragma unroll
            for (int c2 = 0; c2 < 4; c2++)
                acc[r][c2] += __popc(a0[r] & b0[c2]) + __popc(a1[r] & b1[c2]);
    }
}

// ---------------------------------------------------------------------------
// Single fused kernel.  Triangular work map (256 units, 256 threads):
//   tid < 240 : off-diag upper 4x4 tile k=tid>>1 (a<b), half h=tid&1
//               -> words [8h, 8h+8)
//   tid >= 240: diagonal tile d=tid-240 -> all 16 words
// Only upper-triangle tiles accumulate; the reduce symmetrizes with max.
// ---------------------------------------------------------------------------
extern __shared__ char smem[];

__global__ __launch_bounds__(NTHR) void fused_nms_kernel(
    const float* __restrict__ mask, float* __restrict__ out)
{
    const unsigned sbase = su32(smem);
    unsigned (*packed)[NINST] = (unsigned (*)[NINST])(smem + SM_PACKED);
    int* s_chunk = (int*)(smem + SM_CHUNK);
    const unsigned mb[2] = {sbase + SM_MBAR, sbase + SM_MBAR + 8};

    const int tid  = threadIdx.x;
    const int lane = tid & 31;
    const int wp   = tid >> 5;          // 8 warps

    if (tid == 0) {
        mbar_init(mb[0], 1);
        mbar_init(mb[1], 1);
        fence_async();
    }

    // ----- triangular work-unit decode (once) -----
    int ti, tj, w0;
    bool diag;
    if (tid < 240) {
        int k = tid >> 1;               // off-diag tile id in [0,120)
        int a = 0, rem = k;
        while (rem >= 15 - a) { rem -= 15 - a; a++; }
        ti = a; tj = a + 1 + rem;
        w0 = (tid & 1) * 8;
        diag = false;
    } else {
        ti = tj = tid - 240;            // diagonal tile id in [0,16)
        w0 = 0;
        diag = true;
    }
    const int i0 = ti * 4, j0 = tj * 4;

    unsigned acc[4][4];
#pragma unroll
    for (int r = 0; r < 4; r++)
#pragma unroll
        for (int c2 = 0; c2 < 4; c2++) acc[r][c2] = 0u;

    // tid0: issue one group (16 instances x 2KB) into buffer half hb.
    auto issue = [&](int g, int hb, int c) {
        const float* src = mask + (size_t)c * CHUNK_VOX + (size_t)(g * GROUP) * V;
        const unsigned dst = sbase + SM_RAW + hb * HALF_BYTES;
        mbar_expect_tx(mb[hb], HALF_BYTES);
#pragma unroll
        for (int jj = 0; jj < GROUP; jj++)
            tma_bulk(dst + jj * CHUNK_BYTES, src + (size_t)jj * V,
                     CHUNK_BYTES, mb[hb]);
    };

    // Prologue: first ticket + groups 0,1 in flight.
    if (tid == 0) {
        int t0 = (int)atomicAdd(&g_ticket, 1u);
        *s_chunk = t0;
        if (t0 < NCHUNK) { issue(0, 0, t0); issue(1, 1, t0); }
    }
    __syncthreads();
    int c = *s_chunk;

    // Pack read address: warp wp owns words 2wp,2wp+1; lane reads 2 voxels.
    const unsigned raw_rd = sbase + SM_RAW + (unsigned)(wp * 64 + lane * 2) * 4u;
    unsigned ph0 = 0, ph1 = 0;
    int nextc = NCHUNK;  // tid0-local

    while (c < NCHUNK) {
#pragma unroll
        for (int g = 0; g < 4; g++) {
            const int hb = g & 1;
            if (hb == 0) { mbar_wait(mb[0], ph0); ph0 ^= 1; }
            else         { mbar_wait(mb[1], ph1); ph1 ^= 1; }

            // Pack 16 instances (fixed even/odd permutation; identical for
            // all instances, so pairwise popcounts are unaffected).
            const unsigned rbase = raw_rd + (unsigned)hb * HALF_BYTES;
#pragma unroll
            for (int jj = 0; jj < GROUP; jj++) {
                uint2 v;
                asm volatile("ld.shared.v2.u32 {%0,%1}, [%2];"
                             : "=r"(v.x), "=r"(v.y)
                             : "r"(rbase + (unsigned)jj * CHUNK_BYTES));
                unsigned b0 = __ballot_sync(0xffffffffu, v.x != 0u);
                unsigned b1 = __ballot_sync(0xffffffffu, v.y != 0u);
                if (lane == 0) {
                    const int j = g * GROUP + jj;
                    packed[wp * 2][j]     = b0;
                    packed[wp * 2 + 1][j] = b1;
                }
            }
            __syncthreads();  // half hb fully consumed; packed cols visible

            if (tid == 0) {
                fence_async();  // order generic reads before async refill
                if (g == 0)      issue(2, 0, c);
                else if (g == 1) issue(3, 1, c);
                else if (g == 2) {
                    nextc = (int)atomicAdd(&g_ticket, 1u);
                    *s_chunk = nextc;   // published by g3's __syncthreads
                    if (nextc < NCHUNK) issue(0, 0, nextc);
                } else {
                    if (nextc < NCHUNK) issue(1, 1, nextc);
                }
            }
        }

        // Phase B: upper-triangle tile accumulation (fully unrolled).
        if (diag) accum_tile<16>(packed, 0, i0, j0, acc);
        else      accum_tile<8>(packed, w0, i0, j0, acc);

        __syncthreads();  // protect packed[] against next chunk's pack writes
        c = *s_chunk;
    }

    // Flush per-block totals (upper-triangle addresses only).
    {
        unsigned* gp =
            g_partial + (unsigned)(blockIdx.x & (NSLOT - 1)) * (NINST * NINST);
#pragma unroll
        for (int r = 0; r < 4; r++)
#pragma unroll
            for (int c2 = 0; c2 < 4; c2++)
                atomicAdd(&gp[(i0 + r) * NINST + (j0 + c2)], acc[r][c2]);
    }
    __threadfence();
    __syncthreads();
    if (tid == 0) *s_chunk = (int)atomicAdd(&g_done, 1u);
    __syncthreads();
    if (*s_chunk != NBLK - 1) return;

    // ------------------- Last block: reduce + NMS + reset -------------------
    unsigned* inter = (unsigned*)smem;             // 16 KB (raw area is dead)
    unsigned* ssc   = (unsigned*)(smem + 16384);

    {   // vectorized reduce of NSLOT slots (L1-bypassing loads)
        const uint4* gp4 = (const uint4*)g_partial;   // [NSLOT][1024] uint4
        uint4* in4 = (uint4*)inter;
        for (int e = tid; e < (NINST * NINST) / 4; e += NTHR) {
            uint4 s = make_uint4(0u, 0u, 0u, 0u);
#pragma unroll
            for (int k = 0; k < NSLOT; k++) {
                uint4 v = __ldcg(&gp4[k * (NINST * NINST / 4) + e]);
                s.x += v.x; s.y += v.y; s.z += v.z; s.w += v.w;
            }
            in4[e] = s;
        }
    }
    __syncthreads();

    {   // symmetrize: lower-triangle tiles were never written (zeros) ->
        // copy the upper value down via max.
        for (int e = tid; e < NINST * NINST; e += NTHR) {
            int i = e >> 6, j = e & 63;
            if (i > j) {
                unsigned hi = inter[j * NINST + i];
                unsigned lo = inter[e];
                inter[e] = hi > lo ? hi : lo;
            }
        }
    }
    __syncthreads();

    {   // reset device state for the next replay
        uint4 z = make_uint4(0u, 0u, 0u, 0u);
        uint4* gz = (uint4*)g_partial;
        for (int e = tid; e < (NSLOT * NINST * NINST) / 4; e += NTHR) gz[e] = z;
        if (tid == 0) { g_ticket = 0u; g_done = 0u; }
    }

    if (tid < NINST) ssc[tid] = inter[tid * NINST + tid];  // score = diagonal
    __syncthreads();

    if (tid < 32) {
        const unsigned sj0 = ssc[lane];
        const unsigned sj1 = ssc[lane + 32];
        unsigned long long ind = ~0ULL;

        for (int i = 0; i < NINST; i++) {
            if (!((ind >> i) & 1ULL)) continue;  // warp-uniform
            const unsigned si  = ssc[i];
            const unsigned in0 = inter[i * NINST + lane];
            const unsigned in1 = inter[i * NINST + lane + 32];
            // iou > 0.5 <=> 2*inter > union (exact integers; counts < 2^23)
            const bool h0 = (2u * in0 > si + sj0 - in0);
            const bool h1 = (2u * in1 > si + sj1 - in1);
            unsigned a0 = __ballot_sync(0xffffffffu, h0 && (si > sj0));
            unsigned a1 = __ballot_sync(0xffffffffu, h1 && (si > sj1));
            unsigned c0 = __ballot_sync(0xffffffffu, h0 && (sj0 > si));
            unsigned c1 = __ballot_sync(0xffffffffu, h1 && (sj1 > si));
            unsigned long long A  = ((unsigned long long)a1 << 32) | a0;
            unsigned long long Bm = ((unsigned long long)c1 << 32) | c0;
            if (A) {
                int jb = __ffsll((long long)A) - 1;   // first break j
                unsigned long long before = (1ULL << jb) - 1ULL;
                if (Bm & before) ind &= ~(1ULL << i); // earlier j beat i first
                ind &= ~(1ULL << jb);
            } else if (Bm) {
                ind &= ~(1ULL << i);
            }
        }
        out[lane]      = (float)((ind >> lane) & 1ULL);
        out[lane + 32] = (float)((ind >> (lane + 32)) & 1ULL);
    }
}

// ---------------------------------------------------------------------------
extern "C" void kernel_launch(void* const* d_in, const int* in_sizes, int n_in,
                              void* d_out, int out_size) {
    const float* mask = (const float*)d_in[0];
    static bool attr_done = false;
    if (!attr_done) {  // host-side attrs: first (pre-capture) call sets them
        cudaFuncSetAttribute(fused_nms_kernel,
                             cudaFuncAttributeMaxDynamicSharedMemorySize,
                             SM_TOTAL);
        cudaFuncSetAttribute(fused_nms_kernel,
                             cudaFuncAttributePreferredSharedMemoryCarveout,
                             cudaSharedmemCarveoutMaxShared);
        attr_done = true;
    }
    fused_nms_kernel<<<NBLK, NTHR, SM_TOTAL>>>(mask, (float*)d_out);
}

// round 7
// speedup vs baseline: 1.1400x; 1.0201x over previous
#include <cuda_runtime.h>
#include <cstdint>

// Fixed shapes: B=1, N=64, X=256, Y=256, Z=32
#define NINST 64
#define V (256*256*32)                 // 2,097,152 voxels / instance
#define CHUNK_VOX 512                  // voxels per chunk per instance
#define CHUNK_BYTES (CHUNK_VOX*4)      // 2048 B per bulk load
#define CHUNK_WORDS 16                 // packed words per chunk per instance
#define NCHUNK (V/CHUNK_VOX)           // 4096 chunks
#define GROUP 16                       // instances per TMA group / mbarrier
#define HALF_BYTES (GROUP*CHUNK_BYTES) // 32 KB per buffer half
#define NTHR 256
#define NBLK 444                       // 148 SMs * 3 resident blocks
#define NSLOT 8                        // partial accumulator slots
#define IMASK 0x0000ffffu              // issuing lanes (tid 0..15)

// Dynamic smem layout
#define SM_RAW     0
#define SM_PACKED  (2*HALF_BYTES)                      // 65536
#define SM_MBAR    (SM_PACKED + CHUNK_WORDS*NINST*4)   // 69632
#define SM_CHUNK   (SM_MBAR + 16)                      // 69648
#define SM_TOTAL   69664

// Device state (zero-initialized at load; the last block of every launch
// restores it to zero, so graph replays start clean).
__device__ unsigned g_partial[NSLOT * NINST * NINST];
__device__ unsigned g_score[NSLOT * NINST];
__device__ unsigned g_ticket;
__device__ unsigned g_done;

// ---------------------------------------------------------------------------
// PTX helpers
// ---------------------------------------------------------------------------
__device__ __forceinline__ unsigned su32(const void* p) {
    return (unsigned)__cvta_generic_to_shared(p);
}
__device__ __forceinline__ void mbar_init(unsigned a, unsigned cnt) {
    asm volatile("mbarrier.init.shared.b64 [%0], %1;" :: "r"(a), "r"(cnt) : "memory");
}
__device__ __forceinline__ void mbar_expect_tx(unsigned a, unsigned tx) {
    asm volatile("mbarrier.arrive.expect_tx.shared.b64 _, [%0], %1;"
                 :: "r"(a), "r"(tx) : "memory");
}
__device__ __forceinline__ void mbar_wait(unsigned a, unsigned parity) {
    asm volatile(
        "{\n\t.reg .pred p;\n\t"
        "WAIT_%=:\n\t"
        "mbarrier.try_wait.parity.acquire.cta.shared::cta.b64 p, [%0], %1, 0x989680;\n\t"
        "@!p bra WAIT_%=;\n\t}"
        :: "r"(a), "r"(parity) : "memory");
}
__device__ __forceinline__ void tma_bulk(unsigned dst, const void* src,
                                         unsigned bytes, unsigned mbar) {
    asm volatile(
        "cp.async.bulk.shared::cta.global.mbarrier::complete_tx::bytes [%0], [%1], %2, [%3];"
        :: "r"(dst), "l"(src), "r"(bytes), "r"(mbar) : "memory");
}
__device__ __forceinline__ void fence_async() {
    asm volatile("fence.proxy.async.shared::cta;" ::: "memory");
}

// Fully-unrolled popcount accumulation over 8 words starting at w0.
__device__ __forceinline__ void accum_tile8(
    const unsigned (*packed)[NINST], int w0, int i0, int j0,
    unsigned (&acc)[4][4])
{
#pragma unroll
    for (int w = 0; w < 8; w += 2) {
        uint4 A0 = *(const uint4*)&packed[w0 + w][i0];
        uint4 B0 = *(const uint4*)&packed[w0 + w][j0];
        uint4 A1 = *(const uint4*)&packed[w0 + w + 1][i0];
        uint4 B1 = *(const uint4*)&packed[w0 + w + 1][j0];
        unsigned a0[4] = {A0.x, A0.y, A0.z, A0.w};
        unsigned b0[4] = {B0.x, B0.y, B0.z, B0.w};
        unsigned a1[4] = {A1.x, A1.y, A1.z, A1.w};
        unsigned b1[4] = {B1.x, B1.y, B1.z, B1.w};
#pragma unroll
        for (int r = 0; r < 4; r++)
#pragma unroll
            for (int c2 = 0; c2 < 4; c2++)
                acc[r][c2] += __popc(a0[r] & b0[c2]) + __popc(a1[r] & b1[c2]);
    }
}

// ---------------------------------------------------------------------------
// Single fused kernel.
//  - TMA issue: 16 lanes (tid 0..15) each fire one 2KB bulk per group.
//  - Scores: accumulated during packing (per-lane, per-warp partials).
//  - Phase B: 240 uniform off-diagonal units (tile k=tid>>1, half=tid&1).
// ---------------------------------------------------------------------------
extern __shared__ char smem[];

__global__ __launch_bounds__(NTHR) void fused_nms_kernel(
    const float* __restrict__ mask, float* __restrict__ out)
{
    const unsigned sbase = su32(smem);
    unsigned (*packed)[NINST] = (unsigned (*)[NINST])(smem + SM_PACKED);
    volatile int* s_chunk = (volatile int*)(smem + SM_CHUNK);
    const unsigned mb[2] = {sbase + SM_MBAR, sbase + SM_MBAR + 8};

    const int tid  = threadIdx.x;
    const int lane = tid & 31;
    const int wp   = tid >> 5;          // 8 warps

    if (tid == 0) {
        mbar_init(mb[0], 1);
        mbar_init(mb[1], 1);
        fence_async();
    }

    // ----- off-diagonal work-unit decode (threads 0..239) -----
    int i0 = 0, j0 = 4, w0 = 0;
    if (tid < 240) {
        int k = tid >> 1;               // off-diag tile id in [0,120)
        int a = 0, rem = k;
        while (rem >= 15 - a) { rem -= 15 - a; a++; }
        i0 = a * 4; j0 = (a + 1 + rem) * 4;
        w0 = (tid & 1) * 8;
    }

    unsigned acc[4][4];
#pragma unroll
    for (int r = 0; r < 4; r++)
#pragma unroll
        for (int c2 = 0; c2 < 4; c2++) acc[r][c2] = 0u;

    unsigned sc0 = 0, sc1 = 0;   // per-warp score partials (lane-indexed)

    // Lane jj (tid<16) fires one 2KB bulk for instance g*16+jj into half hb.
    auto lane_issue = [&](int g, int hb, int c) {
        const float* src =
            mask + (size_t)c * CHUNK_VOX + (size_t)(g * GROUP + tid) * V;
        tma_bulk(sbase + SM_RAW + hb * HALF_BYTES + tid * CHUNK_BYTES,
                 src, CHUNK_BYTES, mb[hb]);
    };

    // Prologue: first ticket, then groups 0,1 in flight (16-lane issue).
    if (tid == 0) *s_chunk = (int)atomicAdd(&g_ticket, 1u);
    __syncthreads();
    int c = *s_chunk;
    if (tid < 16 && c < NCHUNK) {
        if (tid == 0) {
            mbar_expect_tx(mb[0], HALF_BYTES);
            mbar_expect_tx(mb[1], HALF_BYTES);
        }
        __syncwarp(IMASK);
        lane_issue(0, 0, c);
        lane_issue(1, 1, c);
    }

    // Pack read address: warp wp owns words 2wp,2wp+1; lane reads 2 voxels.
    const unsigned raw_rd = sbase + SM_RAW + (unsigned)(wp * 64 + lane * 2) * 4u;
    unsigned ph0 = 0, ph1 = 0;
    int nextc = NCHUNK;   // issuing-lane local (set at g==2)

    while (c < NCHUNK) {
#pragma unroll
        for (int g = 0; g < 4; g++) {
            const int hb = g & 1;
            if (hb == 0) { mbar_wait(mb[0], ph0); ph0 ^= 1; }
            else         { mbar_wait(mb[1], ph1); ph1 ^= 1; }

            // Pack 16 instances (fixed even/odd permutation, identical for
            // all instances -> pairwise popcounts unaffected) + scores.
            const unsigned rbase = raw_rd + (unsigned)hb * HALF_BYTES;
#pragma unroll
            for (int jj = 0; jj < GROUP; jj++) {
                uint2 v;
                asm volatile("ld.shared.v2.u32 {%0,%1}, [%2];"
                             : "=r"(v.x), "=r"(v.y)
                             : "r"(rbase + (unsigned)jj * CHUNK_BYTES));
                unsigned b0 = __ballot_sync(0xffffffffu, v.x != 0u);
                unsigned b1 = __ballot_sync(0xffffffffu, v.y != 0u);
                const int j = g * GROUP + jj;
                if (lane == 0) {
                    packed[wp * 2][j]     = b0;
                    packed[wp * 2 + 1][j] = b1;
                }
                // score partial for instance j lands in lane (j&31)
                unsigned p = __popc(b0) + __popc(b1);
                if (j < 32) { if (lane == j)        sc0 += p; }
                else        { if (lane == (j - 32)) sc1 += p; }
            }
            __syncthreads();  // half hb fully consumed; packed cols visible

            // Refill half hb (16-lane TMA issue).
            if (tid < 16) {
                fence_async();  // order generic LDS reads before async refill
                if (g == 0) {
                    if (tid == 0) mbar_expect_tx(mb[0], HALF_BYTES);
                    __syncwarp(IMASK);
                    lane_issue(2, 0, c);
                } else if (g == 1) {
                    if (tid == 0) mbar_expect_tx(mb[1], HALF_BYTES);
                    __syncwarp(IMASK);
                    lane_issue(3, 1, c);
                } else if (g == 2) {
                    if (tid == 0) *s_chunk = (int)atomicAdd(&g_ticket, 1u);
                    __syncwarp(IMASK);
                    nextc = *s_chunk;
                    if (nextc < NCHUNK) {
                        if (tid == 0) mbar_expect_tx(mb[0], HALF_BYTES);
                        __syncwarp(IMASK);
                        lane_issue(0, 0, nextc);
                    }
                } else {
                    if (nextc < NCHUNK) {
                        if (tid == 0) mbar_expect_tx(mb[1], HALF_BYTES);
                        __syncwarp(IMASK);
                        lane_issue(1, 1, nextc);
                    }
                }
            }
        }

        // Phase B: uniform off-diagonal accumulation (threads 0..239).
        if (tid < 240) accum_tile8(packed, w0, i0, j0, acc);

        __syncthreads();  // protect packed[] against next chunk's pack writes
        c = *s_chunk;
    }

    // Flush per-block totals (upper-triangle addresses + score partials).
    {
        unsigned* gp =
            g_partial + (unsigned)(blockIdx.x & (NSLOT - 1)) * (NINST * NINST);
        if (tid < 240) {
#pragma unroll
            for (int r = 0; r < 4; r++)
#pragma unroll
                for (int c2 = 0; c2 < 4; c2++)
                    atomicAdd(&gp[(i0 + r) * NINST + (j0 + c2)], acc[r][c2]);
        }
        unsigned* gs = g_score + (unsigned)(blockIdx.x & (NSLOT - 1)) * NINST;
        atomicAdd(&gs[lane], sc0);
        atomicAdd(&gs[lane + 32], sc1);
    }
    __threadfence();
    __syncthreads();
    if (tid == 0) *s_chunk = (int)atomicAdd(&g_done, 1u);
    __syncthreads();
    if (*s_chunk != NBLK - 1) return;

    // ------------------- Last block: reduce + NMS + reset -------------------
    unsigned* inter = (unsigned*)smem;             // 16 KB (raw area is dead)
    unsigned* ssc   = (unsigned*)(smem + 16384);

    {   // vectorized reduce of NSLOT slots (L1-bypassing loads)
        const uint4* gp4 = (const uint4*)g_partial;   // [NSLOT][1024] uint4
        uint4* in4 = (uint4*)inter;
        for (int e = tid; e < (NINST * NINST) / 4; e += NTHR) {
            uint4 s = make_uint4(0u, 0u, 0u, 0u);
#pragma unroll
            for (int k = 0; k < NSLOT; k++) {
                uint4 v = __ldcg(&gp4[k * (NINST * NINST / 4) + e]);
                s.x += v.x; s.y += v.y; s.z += v.z; s.w += v.w;
            }
            in4[e] = s;
        }
        if (tid < NINST) {
            unsigned s = 0;
#pragma unroll
            for (int k = 0; k < NSLOT; k++) s += __ldcg(&g_score[k * NINST + tid]);
            ssc[tid] = s;
        }
    }
    __syncthreads();

    {   // symmetrize: lower-triangle tiles were never written (zeros) ->
        // copy the upper value down via max. Diagonal cells stay 0 (harmless:
        // j==i then gives hit=false in the NMS loop below).
        for (int e = tid; e < NINST * NINST; e += NTHR) {
            int i = e >> 6, j = e & 63;
            if (i > j) {
                unsigned hi = inter[j * NINST + i];
                unsigned lo = inter[e];
                inter[e] = hi > lo ? hi : lo;
            }
        }
    }
    __syncthreads();

    {   // reset device state for the next replay
        uint4 z = make_uint4(0u, 0u, 0u, 0u);
        uint4* gz = (uint4*)g_partial;
        for (int e = tid; e < (NSLOT * NINST * NINST) / 4; e += NTHR) gz[e] = z;
        if (tid < NSLOT * NINST) g_score[tid] = 0u;
        if (tid == 0) { g_ticket = 0u; g_done = 0u; }
    }
    __syncthreads();

    if (tid < 32) {
        const unsigned sj0 = ssc[lane];
        const unsigned sj1 = ssc[lane + 32];
        unsigned long long ind = ~0ULL;

        for (int i = 0; i < NINST; i++) {
            if (!((ind >> i) & 1ULL)) continue;  // warp-uniform
            const unsigned si  = ssc[i];
            const unsigned in0 = inter[i * NINST + lane];
            const unsigned in1 = inter[i * NINST + lane + 32];
            // iou > 0.5 <=> 2*inter > union (exact integers; counts < 2^23)
            const bool h0 = (2u * in0 > si + sj0 - in0);
            const bool h1 = (2u * in1 > si + sj1 - in1);
            unsigned a0 = __ballot_sync(0xffffffffu, h0 && (si > sj0));
            unsigned a1 = __ballot_sync(0xffffffffu, h1 && (si > sj1));
            unsigned c0 = __ballot_sync(0xffffffffu, h0 && (sj0 > si));
            unsigned c1 = __ballot_sync(0xffffffffu, h1 && (sj1 > si));
            unsigned long long A  = ((unsigned long long)a1 << 32) | a0;
            unsigned long long Bm = ((unsigned long long)c1 << 32) | c0;
            if (A) {
                int jb = __ffsll((long long)A) - 1;   // first break j
                unsigned long long before = (1ULL << jb) - 1ULL;
                if (Bm & before) ind &= ~(1ULL << i); // earlier j beat i first
                ind &= ~(1ULL << jb);
            } else if (Bm) {
                ind &= ~(1ULL << i);
            }
        }
        out[lane]      = (float)((ind >> lane) & 1ULL);
        out[lane + 32] = (float)((ind >> (lane + 32)) & 1ULL);
    }
}

// ---------------------------------------------------------------------------
extern "C" void kernel_launch(void* const* d_in, const int* in_sizes, int n_in,
                              void* d_out, int out_size) {
    const float* mask = (const float*)d_in[0];
    static bool attr_done = false;
    if (!attr_done) {  // host-side attrs: first (pre-capture) call sets them
        cudaFuncSetAttribute(fused_nms_kernel,
                             cudaFuncAttributeMaxDynamicSharedMemorySize,
                             SM_TOTAL);
        cudaFuncSetAttribute(fused_nms_kernel,
                             cudaFuncAttributePreferredSharedMemoryCarveout,
                             cudaSharedmemCarveoutMaxShared);
        attr_done = true;
    }
    fused_nms_kernel<<<NBLK, NTHR, SM_TOTAL>>>(mask, (float*)d_out);
}